// round 6
// baseline (speedup 1.0000x reference)
#include <cuda_runtime.h>
#include <cuda_bf16.h>

#define MAXN 50048
#define MAXE 800256
#define NG 128

typedef unsigned long long u64;

// ---------------- device scratch ----------------
__device__ float g_fs[MAXN * 256];
__device__ float g_fd[MAXN * 256];
__device__ float g_h[MAXN * 64];
__device__ int   g_cnt[MAXN];
__device__ int   g_rowptr[MAXN + 1];
__device__ int   g_cursor[MAXN];
__device__ int   g_csrsrc[MAXE];
__device__ int   g_gcnt[NG];
__device__ float g_bnsum[64];
__device__ float g_bnsq[64];
__device__ float g_pooled[NG * 64];
__device__ float g_cat[NG * 192];

__device__ __forceinline__ float lrelu(float x) { return x > 0.f ? x : 0.2f * x; }

__device__ __forceinline__ u64 dup2(float v) {
    u64 r; asm("mov.b64 %0, {%1, %1};" : "=l"(r) : "f"(v)); return r;
}
__device__ __forceinline__ void fma2(u64& d, u64 a, u64 b) {
    asm("fma.rn.f32x2 %0, %1, %2, %0;" : "+l"(d) : "l"(a), "l"(b));
}
__device__ __forceinline__ float2 unpk(u64 v) {
    float2 f; asm("mov.b64 {%0, %1}, %2;" : "=f"(f.x), "=f"(f.y) : "l"(v)); return f;
}

// ================= CSR build (once per launch) =================
__global__ void hist_zero(int N) {
    int i = blockIdx.x * blockDim.x + threadIdx.x;
    if (i < N) g_cnt[i] = 0;
    if (i < NG) g_gcnt[i] = 0;
}
__global__ void hist_kernel(const int* __restrict__ dst, int E) {
    int i = blockIdx.x * blockDim.x + threadIdx.x;
    int stride = gridDim.x * blockDim.x;
    for (int e = i; e < E; e += stride) atomicAdd(&g_cnt[dst[e]], 1);
}
__global__ void gcnt_kernel(const int* __restrict__ gid, int N) {
    __shared__ int h[NG];
    int t = threadIdx.x;
    for (int j = t; j < NG; j += 256) h[j] = 0;
    __syncthreads();
    for (int i = blockIdx.x * blockDim.x + t; i < N; i += gridDim.x * blockDim.x)
        atomicAdd(&h[gid[i]], 1);
    __syncthreads();
    for (int j = t; j < NG; j += 256) if (h[j]) atomicAdd(&g_gcnt[j], h[j]);
}
__global__ __launch_bounds__(1024) void scan_kernel(int N, int E) {
    __shared__ int warpsum[32];
    int t = threadIdx.x;
    int chunk = (N + 1023) >> 10;
    int b = t * chunk, e = min(b + chunk, N);
    int s = 0;
    for (int i = b; i < e; i++) s += g_cnt[i];
    int lane = t & 31, wid = t >> 5;
    int v = s;
#pragma unroll
    for (int o = 1; o < 32; o <<= 1) {
        int u = __shfl_up_sync(0xffffffffu, v, o);
        if (lane >= o) v += u;
    }
    if (lane == 31) warpsum[wid] = v;
    __syncthreads();
    if (wid == 0) {
        int w = warpsum[lane];
#pragma unroll
        for (int o = 1; o < 32; o <<= 1) {
            int u = __shfl_up_sync(0xffffffffu, w, o);
            if (lane >= o) w += u;
        }
        warpsum[lane] = w;
    }
    __syncthreads();
    int offset = (wid > 0 ? warpsum[wid - 1] : 0) + (v - s);
    int run = offset;
    for (int i = b; i < e; i++) {
        g_rowptr[i] = run;
        g_cursor[i] = run;
        run += g_cnt[i];
    }
    if (t == 1023) g_rowptr[N] = E;
}
__global__ void scatter_kernel(const int* __restrict__ src, const int* __restrict__ dst, int E) {
    int i = blockIdx.x * blockDim.x + threadIdx.x;
    int stride = gridDim.x * blockDim.x;
    for (int e = i; e < E; e += stride) {
        int p = atomicAdd(&g_cursor[dst[e]], 1);
        g_csrsrc[p] = src[e];
    }
}

// ================= per-layer small init =================
__global__ void zero_small() {
    int i = blockIdx.x * blockDim.x + threadIdx.x;
    if (i < NG * 64) g_pooled[i] = 0.f;
    if (i < 64) { g_bnsum[i] = 0.f; g_bnsq[i] = 0.f; }
}

// ================= node GEMM (packed f32x2), BN of prev layer folded into load =================
#define HS_PITCH 130
__global__ __launch_bounds__(256, 2) void gemm_kernel(
    const float* __restrict__ feat, int use_feat, int N,
    const float* __restrict__ Ws, const float* __restrict__ bs,
    const float* __restrict__ Wd, const float* __restrict__ bd,
    const float* __restrict__ pg, const float* __restrict__ pb)
{
    extern __shared__ float smem[];
    float* hs = smem;                    // [64][130] transposed: hs[k][row]
    float* ws = smem + 64 * HS_PITCH;    // [64][128]
    __shared__ float snorm[128];         // scale[64], bias[64]

    const float* H = use_feat ? feat : g_h;
    const float* W; const float* B; float* out;
    if (blockIdx.z == 0) { W = Ws; B = bs; out = g_fs; }
    else                 { W = Wd; B = bd; out = g_fd; }
    int col0 = blockIdx.y * 128;
    int r0 = blockIdx.x * 128;
    int tid = threadIdx.x;

    if (!use_feat) {
        if (tid < 64) {
            float invN = 1.f / (float)N;
            float mu = g_bnsum[tid] * invN;
            float var = g_bnsq[tid] * invN - mu * mu;
            float sc = pg[tid] * rsqrtf(var + 1e-5f);
            snorm[tid] = sc;
            snorm[64 + tid] = pb[tid] - mu * sc;
        }
        __syncthreads();
    }

#pragma unroll
    for (int it = 0; it < 8; it++) {
        int idx = tid + it * 256;
        int r = idx >> 4;
        int k = (idx & 15) << 2;
        float4 v = make_float4(0.f, 0.f, 0.f, 0.f);
        if (r0 + r < N) v = *(const float4*)(H + (size_t)(r0 + r) * 64 + k);
        if (!use_feat) {
            v.x = v.x * snorm[k + 0] + snorm[64 + k + 0];
            v.y = v.y * snorm[k + 1] + snorm[64 + k + 1];
            v.z = v.z * snorm[k + 2] + snorm[64 + k + 2];
            v.w = v.w * snorm[k + 3] + snorm[64 + k + 3];
        }
        hs[(k + 0) * HS_PITCH + r] = v.x;
        hs[(k + 1) * HS_PITCH + r] = v.y;
        hs[(k + 2) * HS_PITCH + r] = v.z;
        hs[(k + 3) * HS_PITCH + r] = v.w;
    }
#pragma unroll
    for (int it = 0; it < 8; it++) {
        int idx = (tid + it * 256) * 4;
        int k = idx >> 7;
        int c = idx & 127;
        *(float4*)(ws + k * 128 + c) = *(const float4*)(W + k * 256 + col0 + c);
    }
    __syncthreads();

    int tx = tid & 15, ty = tid >> 4;
    u64 acc[4][8];
#pragma unroll
    for (int rp = 0; rp < 4; rp++)
#pragma unroll
        for (int c = 0; c < 8; c++) acc[rp][c] = 0ULL;

    const float* hbase = hs + ty * 8;
    const float* wbase = ws + tx * 8;
#pragma unroll 8
    for (int k = 0; k < 64; k++) {
        u64 a0 = *(const u64*)(hbase + k * HS_PITCH + 0);
        u64 a1 = *(const u64*)(hbase + k * HS_PITCH + 2);
        u64 a2 = *(const u64*)(hbase + k * HS_PITCH + 4);
        u64 a3 = *(const u64*)(hbase + k * HS_PITCH + 6);
        float4 w0 = *(const float4*)(wbase + k * 128);
        float4 w1 = *(const float4*)(wbase + k * 128 + 4);
        float wv[8] = {w0.x, w0.y, w0.z, w0.w, w1.x, w1.y, w1.z, w1.w};
#pragma unroll
        for (int c = 0; c < 8; c++) {
            u64 bcol = dup2(wv[c]);
            fma2(acc[0][c], a0, bcol);
            fma2(acc[1][c], a1, bcol);
            fma2(acc[2][c], a2, bcol);
            fma2(acc[3][c], a3, bcol);
        }
    }

    float4 bb0 = *(const float4*)(B + col0 + tx * 8);
    float4 bb1 = *(const float4*)(B + col0 + tx * 8 + 4);
    float bias[8] = {bb0.x, bb0.y, bb0.z, bb0.w, bb1.x, bb1.y, bb1.z, bb1.w};
#pragma unroll
    for (int rp = 0; rp < 4; rp++) {
        int grA = r0 + ty * 8 + rp * 2;
        int grB = grA + 1;
        float oa[8], ob[8];
#pragma unroll
        for (int c = 0; c < 8; c++) {
            float2 f = unpk(acc[rp][c]);
            oa[c] = f.x + bias[c];
            ob[c] = f.y + bias[c];
        }
        if (grA < N) {
            float* p = out + (size_t)grA * 256 + col0 + tx * 8;
            *(float4*)p = make_float4(oa[0], oa[1], oa[2], oa[3]);
            *(float4*)(p + 4) = make_float4(oa[4], oa[5], oa[6], oa[7]);
        }
        if (grB < N) {
            float* p = out + (size_t)grB * 256 + col0 + tx * 8;
            *(float4*)p = make_float4(ob[0], ob[1], ob[2], ob[3]);
            *(float4*)(p + 4) = make_float4(ob[4], ob[5], ob[6], ob[7]);
        }
    }
}

// ================= fused edge aggregation: shift-free softmax, software pipelined =================
struct AggState {
    float den;
    float ac[8];
};
__device__ __forceinline__ void agg_pair(
    AggState& st,
    float4 xa0, float4 xa1, float4 xb0, float4 xb1,
    float4 a0, float4 a1, float4 y0, float4 y1)
{
    float p0 = a0.x * lrelu(xa0.x + y0.x) + a0.y * lrelu(xa0.y + y0.y)
             + a0.z * lrelu(xa0.z + y0.z) + a0.w * lrelu(xa0.w + y0.w)
             + a1.x * lrelu(xa1.x + y1.x) + a1.y * lrelu(xa1.y + y1.y)
             + a1.z * lrelu(xa1.z + y1.z) + a1.w * lrelu(xa1.w + y1.w);
    float p1 = a0.x * lrelu(xb0.x + y0.x) + a0.y * lrelu(xb0.y + y0.y)
             + a0.z * lrelu(xb0.z + y0.z) + a0.w * lrelu(xb0.w + y0.w)
             + a1.x * lrelu(xb1.x + y1.x) + a1.y * lrelu(xb1.y + y1.y)
             + a1.z * lrelu(xb1.z + y1.z) + a1.w * lrelu(xb1.w + y1.w);
    p0 += __shfl_xor_sync(0xffffffffu, p0, 1);
    p1 += __shfl_xor_sync(0xffffffffu, p1, 1);
    p0 += __shfl_xor_sync(0xffffffffu, p0, 2);
    p1 += __shfl_xor_sync(0xffffffffu, p1, 2);
    p0 += __shfl_xor_sync(0xffffffffu, p0, 4);
    p1 += __shfl_xor_sync(0xffffffffu, p1, 4);
    float w0 = __expf(p0), w1 = __expf(p1);
    st.den += w0 + w1;
    st.ac[0] += w0 * xa0.x + w1 * xb0.x;
    st.ac[1] += w0 * xa0.y + w1 * xb0.y;
    st.ac[2] += w0 * xa0.z + w1 * xb0.z;
    st.ac[3] += w0 * xa0.w + w1 * xb0.w;
    st.ac[4] += w0 * xa1.x + w1 * xb1.x;
    st.ac[5] += w0 * xa1.y + w1 * xb1.y;
    st.ac[6] += w0 * xa1.z + w1 * xb1.z;
    st.ac[7] += w0 * xa1.w + w1 * xb1.w;
}

__global__ __launch_bounds__(256) void agg_kernel(const float* __restrict__ attn,
                                                  const int* __restrict__ gid, int N)
{
    __shared__ float bsum[64], bsq[64];
    __shared__ float sp[4][64];
    __shared__ int sg0, sspan;
    int t = threadIdx.x;
    if (t < 64) { bsum[t] = 0.f; bsq[t] = 0.f; }
    sp[t >> 6][t & 63] = 0.f;
    int n0 = blockIdx.x * 8;
    int nb_end = min(n0 + 8, N);
    if (t == 0) { int a = gid[n0], z = gid[nb_end - 1]; sg0 = a; sspan = z - a + 1; }
    __syncthreads();

    int lane = t & 31;
    int head = lane >> 3, dp = lane & 7;
    int off = head * 64 + dp * 8;
    int n = n0 + (t >> 5);

    if (n < N) {
        float4 a0 = *(const float4*)(attn + off);
        float4 a1 = *(const float4*)(attn + off + 4);
        const float* fdp_ = g_fd + (size_t)n * 256 + off;
        float4 y0 = *(const float4*)fdp_;
        float4 y1 = *(const float4*)(fdp_ + 4);

        int beg = g_rowptr[n], end = g_rowptr[n + 1];
        AggState st;
        st.den = 0.f;
#pragma unroll
        for (int j = 0; j < 8; j++) st.ac[j] = 0.f;

        int i = beg;
        if (end - beg >= 2) {
            int s0 = g_csrsrc[i], s1 = g_csrsrc[i + 1];
            const float* f0 = g_fs + (size_t)s0 * 256 + off;
            const float* f1 = g_fs + (size_t)s1 * 256 + off;
            float4 xa0 = *(const float4*)f0, xa1 = *(const float4*)(f0 + 4);
            float4 xb0 = *(const float4*)f1, xb1 = *(const float4*)(f1 + 4);
            for (; i + 4 <= end; i += 2) {
                int s2 = g_csrsrc[i + 2], s3 = g_csrsrc[i + 3];
                const float* f2 = g_fs + (size_t)s2 * 256 + off;
                const float* f3 = g_fs + (size_t)s3 * 256 + off;
                float4 ya0 = *(const float4*)f2, ya1 = *(const float4*)(f2 + 4);
                float4 yb0 = *(const float4*)f3, yb1 = *(const float4*)(f3 + 4);
                agg_pair(st, xa0, xa1, xb0, xb1, a0, a1, y0, y1);
                xa0 = ya0; xa1 = ya1; xb0 = yb0; xb1 = yb1;
            }
            agg_pair(st, xa0, xa1, xb0, xb1, a0, a1, y0, y1);
            i += 2;
        }
        for (; i < end; i++) {
            int s0 = g_csrsrc[i];
            const float* f0 = g_fs + (size_t)s0 * 256 + off;
            float4 x00 = *(const float4*)f0, x01 = *(const float4*)(f0 + 4);
            float p0 = a0.x * lrelu(x00.x + y0.x) + a0.y * lrelu(x00.y + y0.y)
                     + a0.z * lrelu(x00.z + y0.z) + a0.w * lrelu(x00.w + y0.w)
                     + a1.x * lrelu(x01.x + y1.x) + a1.y * lrelu(x01.y + y1.y)
                     + a1.z * lrelu(x01.z + y1.z) + a1.w * lrelu(x01.w + y1.w);
            p0 += __shfl_xor_sync(0xffffffffu, p0, 1);
            p0 += __shfl_xor_sync(0xffffffffu, p0, 2);
            p0 += __shfl_xor_sync(0xffffffffu, p0, 4);
            float w0 = __expf(p0);
            st.den += w0;
            st.ac[0] += w0 * x00.x;
            st.ac[1] += w0 * x00.y;
            st.ac[2] += w0 * x00.z;
            st.ac[3] += w0 * x00.w;
            st.ac[4] += w0 * x01.x;
            st.ac[5] += w0 * x01.y;
            st.ac[6] += w0 * x01.z;
            st.ac[7] += w0 * x01.w;
        }
        float inv = (end > beg) ? (0.25f / st.den) : 0.f;
        float v[8];
#pragma unroll
        for (int j = 0; j < 8; j++) v[j] = fmaxf(st.ac[j], 0.f) * inv;
#pragma unroll
        for (int j = 0; j < 8; j++) {
            v[j] += __shfl_xor_sync(0xffffffffu, v[j], 8);
            v[j] += __shfl_xor_sync(0xffffffffu, v[j], 16);
        }
        if (head == 0) {
            *(float4*)(g_h + (size_t)n * 64 + dp * 8)     = make_float4(v[0], v[1], v[2], v[3]);
            *(float4*)(g_h + (size_t)n * 64 + dp * 8 + 4) = make_float4(v[4], v[5], v[6], v[7]);
            int gg = gid[n];
            bool fast = (sspan <= 4);
#pragma unroll
            for (int j = 0; j < 8; j++) {
                int d = dp * 8 + j;
                atomicAdd(&bsum[d], v[j]);
                atomicAdd(&bsq[d], v[j] * v[j]);
                if (fast) atomicAdd(&sp[gg - sg0][d], v[j]);
                else      atomicAdd(&g_pooled[gg * 64 + d], v[j]);
            }
        }
    }
    __syncthreads();
    if (t < 64) {
        atomicAdd(&g_bnsum[t], bsum[t]);
        atomicAdd(&g_bnsq[t], bsq[t]);
    }
    if (sspan <= 4) {
        for (int j = t; j < sspan * 64; j += 256) {
            float val = sp[j >> 6][j & 63];
            if (val != 0.f) atomicAdd(&g_pooled[(sg0 + (j >> 6)) * 64 + (j & 63)], val);
        }
    }
}

// ================= per-layer pooled MLP + BN -> g_cat (with raw-pool correction) =================
__global__ __launch_bounds__(256) void pool_mlp(
    int li, int N, const float* __restrict__ bng, const float* __restrict__ bnb,
    const float* __restrict__ W, const float* __restrict__ B,
    const float* __restrict__ g, const float* __restrict__ bt)
{
    __shared__ float P[128 * 64];
    __shared__ float R[128 * 64];
    __shared__ float mu1[64], iv1[64];
    __shared__ float sc_[64], bi_[64];
    int t = threadIdx.x;
    int c = t & 63, rb = t >> 6;

    if (t < 64) {
        float invN = 1.f / (float)N;
        float mu = g_bnsum[t] * invN;
        float var = g_bnsq[t] * invN - mu * mu;
        float sc = bng[t] * rsqrtf(var + 1e-5f);
        sc_[t] = sc;
        bi_[t] = bnb[t] - mu * sc;
    }
    __syncthreads();
    for (int j = 0; j < 32; j++) {
        int r = rb + j * 4;
        P[r * 64 + c] = sc_[c] * g_pooled[r * 64 + c] + (float)g_gcnt[r] * bi_[c];
    }
    __syncthreads();

    for (int j = 0; j < 32; j++) {
        int r = rb + j * 4;
        float acc = B[c];
        for (int k = 0; k < 64; k++) acc += P[r * 64 + k] * W[k * 64 + c];
        R[r * 64 + c] = fmaxf(acc, 0.f);
    }
    __syncthreads();
    if (t < 64) {
        float s = 0.f, q = 0.f;
        for (int r = 0; r < 128; r++) { float v = R[r * 64 + t]; s += v; q += v * v; }
        float mu = s * (1.f / 128.f);
        float var = q * (1.f / 128.f) - mu * mu;
        mu1[t] = mu; iv1[t] = rsqrtf(var + 1e-5f);
    }
    __syncthreads();
    for (int j = 0; j < 32; j++) {
        int r = rb + j * 4;
        g_cat[r * 192 + li * 64 + c] = (R[r * 64 + c] - mu1[c]) * iv1[c] * g[c] + bt[c];
    }
}

// ================= final head =================
__global__ __launch_bounds__(256) void final_kernel(
    const float* __restrict__ blW, const float* __restrict__ blb,
    const float* __restrict__ blg, const float* __restrict__ blbt,
    const float* __restrict__ llW, const float* __restrict__ llb,
    const float* __restrict__ llg, const float* __restrict__ llbt,
    float* __restrict__ out, int write_hh)
{
    __shared__ float S1[128 * 64];
    __shared__ float S2[128 * 10];
    __shared__ float mu1[64], iv1[64];
    __shared__ float mu2[10], iv2[10];
    int t = threadIdx.x;
    int c = t & 63, rb = t >> 6;

    for (int j = 0; j < 32; j++) {
        int r = rb + j * 4;
        float acc = blb[c];
        for (int k = 0; k < 192; k++) acc += g_cat[r * 192 + k] * blW[k * 64 + c];
        S1[r * 64 + c] = fmaxf(acc, 0.f);
    }
    __syncthreads();

    if (t < 64) {
        float s = 0.f, q = 0.f;
        for (int r = 0; r < 128; r++) { float v = S1[r * 64 + t]; s += v; q += v * v; }
        float mu = s * (1.f / 128.f);
        float var = q * (1.f / 128.f) - mu * mu;
        mu1[t] = mu; iv1[t] = rsqrtf(var + 1e-5f);
    }
    __syncthreads();
    for (int j = 0; j < 32; j++) {
        int r = rb + j * 4;
        float v = (S1[r * 64 + c] - mu1[c]) * iv1[c] * blg[c] + blbt[c];
        S1[r * 64 + c] = v;
        if (write_hh) out[1280 + r * 64 + c] = v;
    }
    __syncthreads();

    if (t < 128) {
        int r = t;
        for (int cc = 0; cc < 10; cc++) {
            float acc = llb[cc];
            for (int k = 0; k < 64; k++) acc += S1[r * 64 + k] * llW[k * 10 + cc];
            S2[r * 10 + cc] = fmaxf(acc, 0.f);
        }
    }
    __syncthreads();
    if (t < 10) {
        float s = 0.f, q = 0.f;
        for (int r = 0; r < 128; r++) { float v = S2[r * 10 + t]; s += v; q += v * v; }
        float mu = s * (1.f / 128.f);
        float var = q * (1.f / 128.f) - mu * mu;
        mu2[t] = mu; iv2[t] = rsqrtf(var + 1e-5f);
    }
    __syncthreads();
    if (t < 128) {
        int r = t;
        float x[10];
        float m = -1e30f;
        for (int cc = 0; cc < 10; cc++) {
            x[cc] = (S2[r * 10 + cc] - mu2[cc]) * iv2[cc] * llg[cc] + llbt[cc];
            m = fmaxf(m, x[cc]);
        }
        float se = 0.f;
        for (int cc = 0; cc < 10; cc++) se += expf(x[cc] - m);
        float lse = m + logf(se);
        for (int cc = 0; cc < 10; cc++) out[r * 10 + cc] = x[cc] - lse;
    }
}

// ================= host launcher =================
extern "C" void kernel_launch(void* const* d_in, const int* in_sizes, int n_in,
                              void* d_out, int out_size)
{
    const float* feat = (const float*)d_in[0];
    const float* Wsrc = (const float*)d_in[1];
    const float* bsrc = (const float*)d_in[2];
    const float* Wdst = (const float*)d_in[3];
    const float* bdst = (const float*)d_in[4];
    const float* attn = (const float*)d_in[5];
    const float* bng  = (const float*)d_in[6];
    const float* bnb  = (const float*)d_in[7];
    const float* lpW  = (const float*)d_in[8];
    const float* lpb  = (const float*)d_in[9];
    const float* lpg  = (const float*)d_in[10];
    const float* lpbt = (const float*)d_in[11];
    const float* blW  = (const float*)d_in[12];
    const float* blb  = (const float*)d_in[13];
    const float* blg  = (const float*)d_in[14];
    const float* blbt = (const float*)d_in[15];
    const float* llW  = (const float*)d_in[16];
    const float* llb  = (const float*)d_in[17];
    const float* llg  = (const float*)d_in[18];
    const float* llbt = (const float*)d_in[19];
    const int* src = (const int*)d_in[20];
    const int* dst = (const int*)d_in[21];
    const int* gid = (const int*)d_in[22];

    int N = in_sizes[0] / 64;
    int E = in_sizes[20];
    float* out = (float*)d_out;

    const int GEMM_SMEM = (64 * HS_PITCH + 64 * 128) * 4;
    cudaFuncSetAttribute(gemm_kernel, cudaFuncAttributeMaxDynamicSharedMemorySize, GEMM_SMEM);

    hist_zero<<<(N + 255) / 256, 256>>>(N);
    hist_kernel<<<1024, 256>>>(dst, E);
    gcnt_kernel<<<64, 256>>>(gid, N);
    scan_kernel<<<1, 1024>>>(N, E);
    scatter_kernel<<<1024, 256>>>(src, dst, E);

    for (int i = 0; i < 3; i++) {
        // gemm first (it consumes previous layer's BN stats), then clear stats for this layer
        gemm_kernel<<<dim3((N + 127) / 128, 2, 2), 256, GEMM_SMEM>>>(
            feat, i == 0 ? 1 : 0, N,
            Wsrc + i * 64 * 256, bsrc + i * 256,
            Wdst + i * 64 * 256, bdst + i * 256,
            i > 0 ? bng + (i - 1) * 64 : bng, i > 0 ? bnb + (i - 1) * 64 : bnb);
        zero_small<<<32, 256>>>();
        agg_kernel<<<(N + 7) / 8, 256>>>(attn + i * 256, gid, N);
        pool_mlp<<<1, 256>>>(i, N, bng + i * 64, bnb + i * 64,
                             lpW + i * 64 * 64, lpb + i * 64, lpg + i * 64, lpbt + i * 64);
    }
    final_kernel<<<1, 256>>>(blW, blb, blg, blbt, llW, llb, llg, llbt,
                             out, out_size >= 128 * 74 ? 1 : 0);
}

// round 7
// speedup vs baseline: 1.2673x; 1.2673x over previous
#include <cuda_runtime.h>
#include <cuda_bf16.h>

#define MAXN 50048
#define MAXE 800256
#define NG 128

typedef unsigned long long u64;

// ---------------- device scratch ----------------
__device__ float g_fs[MAXN * 256];
__device__ float g_fd[MAXN * 256];
__device__ float g_h[MAXN * 64];
__device__ int   g_cnt[MAXN];
__device__ int   g_rowptr[MAXN + 1];
__device__ int   g_cursor[MAXN];
__device__ int   g_csrsrc[MAXE];
__device__ int   g_blksum[64];
__device__ int   g_blkoff[64];
__device__ float g_bnsum[64];
__device__ float g_bnsq[64];
__device__ float g_pooled[NG * 64];
__device__ float g_cat[NG * 192];

__device__ __forceinline__ float lrelu(float x) { return x > 0.f ? x : 0.2f * x; }

__device__ __forceinline__ u64 dup2(float v) {
    u64 r; asm("mov.b64 %0, {%1, %1};" : "=l"(r) : "f"(v)); return r;
}
__device__ __forceinline__ void fma2(u64& d, u64 a, u64 b) {
    asm("fma.rn.f32x2 %0, %1, %2, %0;" : "+l"(d) : "l"(a), "l"(b));
}
__device__ __forceinline__ float2 unpk(u64 v) {
    float2 f; asm("mov.b64 {%0, %1}, %2;" : "=f"(f.x), "=f"(f.y) : "l"(v)); return f;
}

// ================= CSR build (once per launch) =================
__global__ void hist_zero(int N) {
    int i = blockIdx.x * blockDim.x + threadIdx.x;
    if (i < N) g_cnt[i] = 0;
}
__global__ void hist_kernel(const int* __restrict__ dst, int E) {
    int i = blockIdx.x * blockDim.x + threadIdx.x;
    int stride = gridDim.x * blockDim.x;
    for (int e = i; e < E; e += stride) atomicAdd(&g_cnt[dst[e]], 1);
}

// --- 3-phase parallel scan over g_cnt ---
__global__ __launch_bounds__(1024) void scan_pre(int N) {
    int i = blockIdx.x * 1024 + threadIdx.x;
    int v = (i < N) ? g_cnt[i] : 0;
    __shared__ int ws[32];
    int lane = threadIdx.x & 31, w = threadIdx.x >> 5;
#pragma unroll
    for (int o = 16; o; o >>= 1) v += __shfl_down_sync(0xffffffffu, v, o);
    if (lane == 0) ws[w] = v;
    __syncthreads();
    if (w == 0) {
        int s = ws[lane];
#pragma unroll
        for (int o = 16; o; o >>= 1) s += __shfl_down_sync(0xffffffffu, s, o);
        if (lane == 0) g_blksum[blockIdx.x] = s;
    }
}
__global__ void scan_mid(int nb) {
    __shared__ int sh[64];
    int t = threadIdx.x;      // 64 threads
    int v = (t < nb) ? g_blksum[t] : 0;
    sh[t] = v;
    __syncthreads();
#pragma unroll
    for (int o = 1; o < 64; o <<= 1) {
        int u = (t >= o) ? sh[t - o] : 0;
        __syncthreads();
        sh[t] += u;
        __syncthreads();
    }
    if (t < nb) g_blkoff[t] = sh[t] - v;   // exclusive
}
__global__ __launch_bounds__(1024) void scan_fin(int N, int E) {
    int i = blockIdx.x * 1024 + threadIdx.x;
    int v = (i < N) ? g_cnt[i] : 0;
    int lane = threadIdx.x & 31, w = threadIdx.x >> 5;
    int inc = v;
#pragma unroll
    for (int o = 1; o < 32; o <<= 1) {
        int u = __shfl_up_sync(0xffffffffu, inc, o);
        if (lane >= o) inc += u;
    }
    __shared__ int ws[32];
    if (lane == 31) ws[w] = inc;
    __syncthreads();
    if (w == 0) {
        int s = ws[lane];
#pragma unroll
        for (int o = 1; o < 32; o <<= 1) {
            int u = __shfl_up_sync(0xffffffffu, s, o);
            if (lane >= o) s += u;
        }
        ws[lane] = s;
    }
    __syncthreads();
    int excl = inc - v + (w > 0 ? ws[w - 1] : 0) + g_blkoff[blockIdx.x];
    if (i < N) { g_rowptr[i] = excl; g_cursor[i] = excl; }
    if (i == N - 1) g_rowptr[N] = E;
}

__global__ void scatter_kernel(const int* __restrict__ src, const int* __restrict__ dst, int E) {
    int i = blockIdx.x * blockDim.x + threadIdx.x;
    int stride = gridDim.x * blockDim.x;
    for (int e = i; e < E; e += stride) {
        int p = atomicAdd(&g_cursor[dst[e]], 1);
        g_csrsrc[p] = src[e];
    }
}

// ================= per-layer small init =================
__global__ void zero_small() {
    int i = blockIdx.x * blockDim.x + threadIdx.x;
    if (i < NG * 64) g_pooled[i] = 0.f;
    if (i < 64) { g_bnsum[i] = 0.f; g_bnsq[i] = 0.f; }
}

// ================= node GEMM with packed f32x2 FFMA =================
#define HS_PITCH 130
__global__ __launch_bounds__(256, 2) void gemm_kernel(
    const float* __restrict__ feat, int use_feat, int N,
    const float* __restrict__ Ws, const float* __restrict__ bs,
    const float* __restrict__ Wd, const float* __restrict__ bd)
{
    extern __shared__ float smem[];
    float* hs = smem;                    // [64][130] transposed: hs[k][row]
    float* ws = smem + 64 * HS_PITCH;    // [64][128]

    const float* H = use_feat ? feat : g_h;
    const float* W; const float* B; float* out;
    if (blockIdx.z == 0) { W = Ws; B = bs; out = g_fs; }
    else                 { W = Wd; B = bd; out = g_fd; }
    int col0 = blockIdx.y * 128;
    int r0 = blockIdx.x * 128;
    int tid = threadIdx.x;

#pragma unroll
    for (int it = 0; it < 8; it++) {
        int idx = tid + it * 256;
        int r = idx >> 4;
        int k = (idx & 15) << 2;
        float4 v = make_float4(0.f, 0.f, 0.f, 0.f);
        if (r0 + r < N) v = *(const float4*)(H + (size_t)(r0 + r) * 64 + k);
        hs[(k + 0) * HS_PITCH + r] = v.x;
        hs[(k + 1) * HS_PITCH + r] = v.y;
        hs[(k + 2) * HS_PITCH + r] = v.z;
        hs[(k + 3) * HS_PITCH + r] = v.w;
    }
#pragma unroll
    for (int it = 0; it < 8; it++) {
        int idx = (tid + it * 256) * 4;
        int k = idx >> 7;
        int c = idx & 127;
        *(float4*)(ws + k * 128 + c) = *(const float4*)(W + k * 256 + col0 + c);
    }
    __syncthreads();

    int tx = tid & 15, ty = tid >> 4;
    u64 acc[4][8];
#pragma unroll
    for (int rp = 0; rp < 4; rp++)
#pragma unroll
        for (int c = 0; c < 8; c++) acc[rp][c] = 0ULL;

    const float* hbase = hs + ty * 8;
    const float* wbase = ws + tx * 8;
#pragma unroll 8
    for (int k = 0; k < 64; k++) {
        u64 a0 = *(const u64*)(hbase + k * HS_PITCH + 0);
        u64 a1 = *(const u64*)(hbase + k * HS_PITCH + 2);
        u64 a2 = *(const u64*)(hbase + k * HS_PITCH + 4);
        u64 a3 = *(const u64*)(hbase + k * HS_PITCH + 6);
        float4 w0 = *(const float4*)(wbase + k * 128);
        float4 w1 = *(const float4*)(wbase + k * 128 + 4);
        float wv[8] = {w0.x, w0.y, w0.z, w0.w, w1.x, w1.y, w1.z, w1.w};
#pragma unroll
        for (int c = 0; c < 8; c++) {
            u64 bcol = dup2(wv[c]);
            fma2(acc[0][c], a0, bcol);
            fma2(acc[1][c], a1, bcol);
            fma2(acc[2][c], a2, bcol);
            fma2(acc[3][c], a3, bcol);
        }
    }

    float4 bb0 = *(const float4*)(B + col0 + tx * 8);
    float4 bb1 = *(const float4*)(B + col0 + tx * 8 + 4);
    float bias[8] = {bb0.x, bb0.y, bb0.z, bb0.w, bb1.x, bb1.y, bb1.z, bb1.w};
#pragma unroll
    for (int rp = 0; rp < 4; rp++) {
        int grA = r0 + ty * 8 + rp * 2;
        int grB = grA + 1;
        float oa[8], ob[8];
#pragma unroll
        for (int c = 0; c < 8; c++) {
            float2 f = unpk(acc[rp][c]);
            oa[c] = f.x + bias[c];
            ob[c] = f.y + bias[c];
        }
        if (grA < N) {
            float* p = out + (size_t)grA * 256 + col0 + tx * 8;
            *(float4*)p = make_float4(oa[0], oa[1], oa[2], oa[3]);
            *(float4*)(p + 4) = make_float4(oa[4], oa[5], oa[6], oa[7]);
        }
        if (grB < N) {
            float* p = out + (size_t)grB * 256 + col0 + tx * 8;
            *(float4*)p = make_float4(ob[0], ob[1], ob[2], ob[3]);
            *(float4*)(p + 4) = make_float4(ob[4], ob[5], ob[6], ob[7]);
        }
    }
}

// ================= fused edge aggregation: online softmax, 2-edge unroll =================
__global__ __launch_bounds__(256) void agg_kernel(const float* __restrict__ attn, int N)
{
    __shared__ float bsum[64], bsq[64];
    int t = threadIdx.x;
    if (t < 64) { bsum[t] = 0.f; bsq[t] = 0.f; }
    __syncthreads();

    int lane = t & 31;
    int head = lane >> 3, dp = lane & 7;
    int off = head * 64 + dp * 8;
    int n = blockIdx.x * 8 + (t >> 5);

    if (n < N) {
        float4 a0 = *(const float4*)(attn + off);
        float4 a1 = *(const float4*)(attn + off + 4);
        const float* fdp_ = g_fd + (size_t)n * 256 + off;
        float4 y0 = *(const float4*)fdp_;
        float4 y1 = *(const float4*)(fdp_ + 4);

        int beg = g_rowptr[n], end = g_rowptr[n + 1];
        float m = -3.0e38f, den = 0.f;
        float ac[8];
#pragma unroll
        for (int j = 0; j < 8; j++) ac[j] = 0.f;

        int i = beg;
        for (; i + 2 <= end; i += 2) {
            int s0 = g_csrsrc[i], s1 = g_csrsrc[i + 1];
            const float* f0 = g_fs + (size_t)s0 * 256 + off;
            const float* f1 = g_fs + (size_t)s1 * 256 + off;
            float4 x00 = *(const float4*)f0;
            float4 x01 = *(const float4*)(f0 + 4);
            float4 x10 = *(const float4*)f1;
            float4 x11 = *(const float4*)(f1 + 4);
            float p0 = a0.x * lrelu(x00.x + y0.x) + a0.y * lrelu(x00.y + y0.y)
                     + a0.z * lrelu(x00.z + y0.z) + a0.w * lrelu(x00.w + y0.w)
                     + a1.x * lrelu(x01.x + y1.x) + a1.y * lrelu(x01.y + y1.y)
                     + a1.z * lrelu(x01.z + y1.z) + a1.w * lrelu(x01.w + y1.w);
            float p1 = a0.x * lrelu(x10.x + y0.x) + a0.y * lrelu(x10.y + y0.y)
                     + a0.z * lrelu(x10.z + y0.z) + a0.w * lrelu(x10.w + y0.w)
                     + a1.x * lrelu(x11.x + y1.x) + a1.y * lrelu(x11.y + y1.y)
                     + a1.z * lrelu(x11.z + y1.z) + a1.w * lrelu(x11.w + y1.w);
            p0 += __shfl_xor_sync(0xffffffffu, p0, 1);
            p1 += __shfl_xor_sync(0xffffffffu, p1, 1);
            p0 += __shfl_xor_sync(0xffffffffu, p0, 2);
            p1 += __shfl_xor_sync(0xffffffffu, p1, 2);
            p0 += __shfl_xor_sync(0xffffffffu, p0, 4);
            p1 += __shfl_xor_sync(0xffffffffu, p1, 4);
            float mn = fmaxf(m, fmaxf(p0, p1));
            float sc = __expf(m - mn);
            float w0 = __expf(p0 - mn);
            float w1 = __expf(p1 - mn);
            den = den * sc + w0 + w1;
            ac[0] = ac[0] * sc + w0 * x00.x + w1 * x10.x;
            ac[1] = ac[1] * sc + w0 * x00.y + w1 * x10.y;
            ac[2] = ac[2] * sc + w0 * x00.z + w1 * x10.z;
            ac[3] = ac[3] * sc + w0 * x00.w + w1 * x10.w;
            ac[4] = ac[4] * sc + w0 * x01.x + w1 * x11.x;
            ac[5] = ac[5] * sc + w0 * x01.y + w1 * x11.y;
            ac[6] = ac[6] * sc + w0 * x01.z + w1 * x11.z;
            ac[7] = ac[7] * sc + w0 * x01.w + w1 * x11.w;
            m = mn;
        }
        if (i < end) {
            int s0 = g_csrsrc[i];
            const float* f0 = g_fs + (size_t)s0 * 256 + off;
            float4 x00 = *(const float4*)f0;
            float4 x01 = *(const float4*)(f0 + 4);
            float p0 = a0.x * lrelu(x00.x + y0.x) + a0.y * lrelu(x00.y + y0.y)
                     + a0.z * lrelu(x00.z + y0.z) + a0.w * lrelu(x00.w + y0.w)
                     + a1.x * lrelu(x01.x + y1.x) + a1.y * lrelu(x01.y + y1.y)
                     + a1.z * lrelu(x01.z + y1.z) + a1.w * lrelu(x01.w + y1.w);
            p0 += __shfl_xor_sync(0xffffffffu, p0, 1);
            p0 += __shfl_xor_sync(0xffffffffu, p0, 2);
            p0 += __shfl_xor_sync(0xffffffffu, p0, 4);
            float mn = fmaxf(m, p0);
            float sc = __expf(m - mn);
            float w0 = __expf(p0 - mn);
            den = den * sc + w0;
            ac[0] = ac[0] * sc + w0 * x00.x;
            ac[1] = ac[1] * sc + w0 * x00.y;
            ac[2] = ac[2] * sc + w0 * x00.z;
            ac[3] = ac[3] * sc + w0 * x00.w;
            ac[4] = ac[4] * sc + w0 * x01.x;
            ac[5] = ac[5] * sc + w0 * x01.y;
            ac[6] = ac[6] * sc + w0 * x01.z;
            ac[7] = ac[7] * sc + w0 * x01.w;
        }
        float inv = (end > beg) ? (0.25f / den) : 0.f;
        float v[8];
#pragma unroll
        for (int j = 0; j < 8; j++) v[j] = fmaxf(ac[j], 0.f) * inv;
#pragma unroll
        for (int j = 0; j < 8; j++) {
            v[j] += __shfl_xor_sync(0xffffffffu, v[j], 8);
            v[j] += __shfl_xor_sync(0xffffffffu, v[j], 16);
        }
        if (head == 0) {
            *(float4*)(g_h + (size_t)n * 64 + dp * 8)     = make_float4(v[0], v[1], v[2], v[3]);
            *(float4*)(g_h + (size_t)n * 64 + dp * 8 + 4) = make_float4(v[4], v[5], v[6], v[7]);
#pragma unroll
            for (int j = 0; j < 8; j++) {
                atomicAdd(&bsum[dp * 8 + j], v[j]);
                atomicAdd(&bsq[dp * 8 + j], v[j] * v[j]);
            }
        }
    }
    __syncthreads();
    if (t < 64) {
        atomicAdd(&g_bnsum[t], bsum[t]);
        atomicAdd(&g_bnsq[t], bsq[t]);
    }
}

// ================= apply BN + graph sum-pool (smem staged; gid sorted) =================
__global__ __launch_bounds__(256) void bn_pool(int N, const float* __restrict__ g,
                                               const float* __restrict__ b,
                                               const int* __restrict__ gid)
{
    __shared__ float sp[4][64];
    __shared__ int sg0, sspan;
    int t = threadIdx.x;
    int n0 = blockIdx.x * 64;
    int nend = min(n0 + 64, N);
    if (n0 >= N) return;
    if (t == 0) { int a = gid[n0], z = gid[nend - 1]; sg0 = a; sspan = z - a + 1; }
    sp[t >> 6][t & 63] = 0.f;
    __syncthreads();

    float invN = 1.f / (float)N;
    int d = t & 63;
    float mu = g_bnsum[d] * invN;
    float var = g_bnsq[d] * invN - mu * mu;
    float scale = rsqrtf(var + 1e-5f) * g[d];
    float bias = b[d] - mu * scale;
    bool fast = (sspan <= 4);
    int g0 = sg0;
    int cnt = (nend - n0) * 64;
    for (int i = t; i < cnt; i += 256) {
        int n = n0 + (i >> 6);
        float v = g_h[(size_t)n * 64 + d] * scale + bias;
        g_h[(size_t)n * 64 + d] = v;
        if (fast) atomicAdd(&sp[gid[n] - g0][d], v);
        else      atomicAdd(&g_pooled[gid[n] * 64 + d], v);
    }
    __syncthreads();
    if (fast) {
        for (int j = t; j < sspan * 64; j += 256)
            atomicAdd(&g_pooled[(g0 + (j >> 6)) * 64 + (j & 63)], sp[j >> 6][j & 63]);
    }
}

// ================= per-layer pooled MLP + BN -> g_cat =================
__global__ __launch_bounds__(256) void pool_mlp(
    int li, const float* __restrict__ W, const float* __restrict__ B,
    const float* __restrict__ g, const float* __restrict__ bt)
{
    __shared__ float R[128 * 64];
    __shared__ float mu1[64], iv1[64];
    int t = threadIdx.x;
    int c = t & 63, rb = t >> 6;
    for (int j = 0; j < 32; j++) {
        int r = rb + j * 4;
        float acc = B[c];
        for (int k = 0; k < 64; k++) acc += g_pooled[r * 64 + k] * W[k * 64 + c];
        R[r * 64 + c] = fmaxf(acc, 0.f);
    }
    __syncthreads();
    if (t < 64) {
        float s = 0.f, q = 0.f;
        for (int r = 0; r < 128; r++) { float v = R[r * 64 + t]; s += v; q += v * v; }
        float mu = s * (1.f / 128.f);
        float var = q * (1.f / 128.f) - mu * mu;
        mu1[t] = mu; iv1[t] = rsqrtf(var + 1e-5f);
    }
    __syncthreads();
    for (int j = 0; j < 32; j++) {
        int r = rb + j * 4;
        g_cat[r * 192 + li * 64 + c] = (R[r * 64 + c] - mu1[c]) * iv1[c] * g[c] + bt[c];
    }
}

// ================= final head =================
__global__ __launch_bounds__(256) void final_kernel(
    const float* __restrict__ blW, const float* __restrict__ blb,
    const float* __restrict__ blg, const float* __restrict__ blbt,
    const float* __restrict__ llW, const float* __restrict__ llb,
    const float* __restrict__ llg, const float* __restrict__ llbt,
    float* __restrict__ out, int write_hh)
{
    __shared__ float S1[128 * 64];
    __shared__ float S2[128 * 10];
    __shared__ float mu1[64], iv1[64];
    __shared__ float mu2[10], iv2[10];
    int t = threadIdx.x;
    int c = t & 63, rb = t >> 6;

    for (int j = 0; j < 32; j++) {
        int r = rb + j * 4;
        float acc = blb[c];
        for (int k = 0; k < 192; k++) acc += g_cat[r * 192 + k] * blW[k * 64 + c];
        S1[r * 64 + c] = fmaxf(acc, 0.f);
    }
    __syncthreads();

    if (t < 64) {
        float s = 0.f, q = 0.f;
        for (int r = 0; r < 128; r++) { float v = S1[r * 64 + t]; s += v; q += v * v; }
        float mu = s * (1.f / 128.f);
        float var = q * (1.f / 128.f) - mu * mu;
        mu1[t] = mu; iv1[t] = rsqrtf(var + 1e-5f);
    }
    __syncthreads();
    for (int j = 0; j < 32; j++) {
        int r = rb + j * 4;
        float v = (S1[r * 64 + c] - mu1[c]) * iv1[c] * blg[c] + blbt[c];
        S1[r * 64 + c] = v;
        if (write_hh) out[1280 + r * 64 + c] = v;
    }
    __syncthreads();

    if (t < 128) {
        int r = t;
        for (int cc = 0; cc < 10; cc++) {
            float acc = llb[cc];
            for (int k = 0; k < 64; k++) acc += S1[r * 64 + k] * llW[k * 10 + cc];
            S2[r * 10 + cc] = fmaxf(acc, 0.f);
        }
    }
    __syncthreads();
    if (t < 10) {
        float s = 0.f, q = 0.f;
        for (int r = 0; r < 128; r++) { float v = S2[r * 10 + t]; s += v; q += v * v; }
        float mu = s * (1.f / 128.f);
        float var = q * (1.f / 128.f) - mu * mu;
        mu2[t] = mu; iv2[t] = rsqrtf(var + 1e-5f);
    }
    __syncthreads();
    if (t < 128) {
        int r = t;
        float x[10];
        float m = -1e30f;
        for (int cc = 0; cc < 10; cc++) {
            x[cc] = (S2[r * 10 + cc] - mu2[cc]) * iv2[cc] * llg[cc] + llbt[cc];
            m = fmaxf(m, x[cc]);
        }
        float se = 0.f;
        for (int cc = 0; cc < 10; cc++) se += expf(x[cc] - m);
        float lse = m + logf(se);
        for (int cc = 0; cc < 10; cc++) out[r * 10 + cc] = x[cc] - lse;
    }
}

// ================= host launcher =================
extern "C" void kernel_launch(void* const* d_in, const int* in_sizes, int n_in,
                              void* d_out, int out_size)
{
    const float* feat = (const float*)d_in[0];
    const float* Wsrc = (const float*)d_in[1];
    const float* bsrc = (const float*)d_in[2];
    const float* Wdst = (const float*)d_in[3];
    const float* bdst = (const float*)d_in[4];
    const float* attn = (const float*)d_in[5];
    const float* bng  = (const float*)d_in[6];
    const float* bnb  = (const float*)d_in[7];
    const float* lpW  = (const float*)d_in[8];
    const float* lpb  = (const float*)d_in[9];
    const float* lpg  = (const float*)d_in[10];
    const float* lpbt = (const float*)d_in[11];
    const float* blW  = (const float*)d_in[12];
    const float* blb  = (const float*)d_in[13];
    const float* blg  = (const float*)d_in[14];
    const float* blbt = (const float*)d_in[15];
    const float* llW  = (const float*)d_in[16];
    const float* llb  = (const float*)d_in[17];
    const float* llg  = (const float*)d_in[18];
    const float* llbt = (const float*)d_in[19];
    const int* src = (const int*)d_in[20];
    const int* dst = (const int*)d_in[21];
    const int* gid = (const int*)d_in[22];

    int N = in_sizes[0] / 64;
    int E = in_sizes[20];
    float* out = (float*)d_out;

    const int GEMM_SMEM = (64 * HS_PITCH + 64 * 128) * 4;
    cudaFuncSetAttribute(gemm_kernel, cudaFuncAttributeMaxDynamicSharedMemorySize, GEMM_SMEM);

    int nb = (N + 1023) / 1024;
    hist_zero<<<(N + 255) / 256, 256>>>(N);
    hist_kernel<<<1024, 256>>>(dst, E);
    scan_pre<<<nb, 1024>>>(N);
    scan_mid<<<1, 64>>>(nb);
    scan_fin<<<nb, 1024>>>(N, E);
    scatter_kernel<<<1024, 256>>>(src, dst, E);

    for (int i = 0; i < 3; i++) {
        zero_small<<<32, 256>>>();
        gemm_kernel<<<dim3((N + 127) / 128, 2, 2), 256, GEMM_SMEM>>>(
            feat, i == 0 ? 1 : 0, N,
            Wsrc + i * 64 * 256, bsrc + i * 256,
            Wdst + i * 64 * 256, bdst + i * 256);
        agg_kernel<<<(N + 7) / 8, 256>>>(attn + i * 256, N);
        bn_pool<<<(N + 63) / 64, 256>>>(N, bng + i * 64, bnb + i * 64, gid);
        pool_mlp<<<1, 256>>>(i, lpW + i * 64 * 64, lpb + i * 64, lpg + i * 64, lpbt + i * 64);
    }
    final_kernel<<<1, 256>>>(blW, blb, blg, blbt, llW, llb, llg, llbt,
                             out, out_size >= 128 * 74 ? 1 : 0);
}